// round 1
// baseline (speedup 1.0000x reference)
#include <cuda_runtime.h>
#include <cstdint>

// Problem constants
#define T_DIM 8
#define C_DIM 4
#define NMAPS (T_DIM * C_DIM)        // 32
#define H_DIM 1024
#define W_DIM 1024
#define NUM_GRID 16
#define NCELLS (NUM_GRID * NUM_GRID) // 256
#define CELL 64
#define THRESH 0.65f
#define NUM_FG 40
#define NUM_BG 1
#define MAX_PTS 42

// Scratch (no allocations allowed -> __device__ globals)
// cell pack: (float bits of cell max << 32) | argmax flat index (earliest)
__device__ unsigned long long g_cellpack[NMAPS * NCELLS];
// per-map min key: (orderable(val) << 32) | index ; atomicMin gives (min val, min idx)
__device__ unsigned long long g_minkey[NMAPS];

__global__ void k_init() {
    if (threadIdx.x < NMAPS) g_minkey[threadIdx.x] = ~0ULL;
}

// ---------------------------------------------------------------------------
// Kernel B: per-cell max/argmax + per-map min/argmin.
// grid = NMAPS * 32 blocks (each block: 8 warps = 8 cells), block = 256 thr.
// ---------------------------------------------------------------------------
__global__ __launch_bounds__(256) void k_cells(const float* __restrict__ sims) {
    const int b    = blockIdx.x;          // 0..1023
    const int m    = b >> 5;              // map id
    const int warp = threadIdx.x >> 5;
    const int lane = threadIdx.x & 31;
    const int cid  = ((b & 31) << 3) + warp;  // 0..255
    const int cy   = cid >> 4;
    const int cx   = cid & 15;

    const float* __restrict__ base = sims + (size_t)m * (H_DIM * W_DIM);
    const int rowsel = lane >> 4;                    // 0/1: which of the 2 rows
    const int col    = (cx << 6) + ((lane & 15) << 2);

    float    maxv = -__int_as_float(0x7f800000) * 1.0f; // -inf
    unsigned maxi = 0u;
    float    minv = __int_as_float(0x7f800000);         // +inf
    unsigned mini = 0u;
    maxv = -minv;

    #pragma unroll 4
    for (int i = 0; i < 32; ++i) {
        const int row = (cy << 6) + (i << 1) + rowsel;
        const unsigned idx = ((unsigned)row << 10) + (unsigned)col;
        const float4 v = *reinterpret_cast<const float4*>(base + idx);
        // strictly-greater keeps earliest index (indices increase per lane)
        if (v.x > maxv) { maxv = v.x; maxi = idx;     }
        if (v.y > maxv) { maxv = v.y; maxi = idx + 1; }
        if (v.z > maxv) { maxv = v.z; maxi = idx + 2; }
        if (v.w > maxv) { maxv = v.w; maxi = idx + 3; }
        if (v.x < minv) { minv = v.x; mini = idx;     }
        if (v.y < minv) { minv = v.y; mini = idx + 1; }
        if (v.z < minv) { minv = v.z; mini = idx + 2; }
        if (v.w < minv) { minv = v.w; mini = idx + 3; }
    }

    // warp lexicographic reduce: (max val, then min idx) / (min val, then min idx)
    #pragma unroll
    for (int o = 16; o > 0; o >>= 1) {
        float    ov = __shfl_down_sync(0xffffffffu, maxv, o);
        unsigned oi = __shfl_down_sync(0xffffffffu, maxi, o);
        if (ov > maxv || (ov == maxv && oi < maxi)) { maxv = ov; maxi = oi; }
        float    nv = __shfl_down_sync(0xffffffffu, minv, o);
        unsigned ni = __shfl_down_sync(0xffffffffu, mini, o);
        if (nv < minv || (nv == minv && ni < mini)) { minv = nv; mini = ni; }
    }

    __shared__ unsigned long long sminkey[8];
    if (lane == 0) {
        g_cellpack[m * NCELLS + cid] =
            ((unsigned long long)__float_as_uint(maxv) << 32) | (unsigned long long)maxi;
        // orderable transform (all values are non-negative floats): bits ^ 0x80000000
        sminkey[warp] =
            ((unsigned long long)(__float_as_uint(minv) ^ 0x80000000u) << 32) |
            (unsigned long long)mini;
    }
    __syncthreads();
    if (threadIdx.x == 0) {
        unsigned long long k = sminkey[0];
        #pragma unroll
        for (int j = 1; j < 8; ++j) k = min(k, sminkey[j]);
        atomicMin(&g_minkey[m], k);
    }
}

// ---------------------------------------------------------------------------
// Kernel C: per-map selection + output assembly.
// grid = NMAPS blocks, block = 256 threads (one per cell).
// ---------------------------------------------------------------------------
__global__ __launch_bounds__(256) void k_select(const int* __restrict__ osz,
                                                float* __restrict__ out,
                                                int write_nums, int nums_off) {
    const int m   = blockIdx.x;
    const int tid = threadIdx.x; // == cell id

    __shared__ float    sval[NCELLS];
    __shared__ unsigned sidx[NCELLS];

    const unsigned long long p = g_cellpack[m * NCELLS + tid];
    const float    v   = __uint_as_float((unsigned)(p >> 32));
    const unsigned idx = (unsigned)p;
    sval[tid] = v;
    sidx[tid] = idx;

    float* __restrict__ orow = out + (size_t)m * (MAX_PTS * 4);
    if (tid < MAX_PTS) {
        float4 z = make_float4(0.f, 0.f, 0.f, 0.f);
        reinterpret_cast<float4*>(orow)[tid] = z;
    }

    const bool valid = (v > THRESH);
    const int  count = __syncthreads_count(valid);   // barrier: sval/zeroing done
    const int  n_valid = count < NUM_FG ? count : NUM_FG;
    const bool any_fg  = (count > 0);

    const int   t  = m / C_DIM;
    const float sx = (float)osz[t * 2 + 1] / (float)W_DIM;
    const float sy = (float)osz[t * 2 + 0] / (float)H_DIM;

    // rank = #cells strictly better: (score desc, cell-id asc) — matches stable argsort
    const float NEGINF = -__int_as_float(0x7f800000);
    const float effv = valid ? v : NEGINF;
    int rank = 0;
    #pragma unroll 8
    for (int j = 0; j < NCELLS; ++j) {
        const float jv = sval[j];
        const float ej = (jv > THRESH) ? jv : NEGINF;
        rank += (int)((ej > effv) || (ej == effv && j < tid));
    }

    if (any_fg) {
        if (valid && rank < NUM_FG) {
            const float px = (float)(idx & (W_DIM - 1));
            const float py = (float)(idx >> 10);
            reinterpret_cast<float4*>(orow)[rank] =
                make_float4(px * sx, py * sy, v, 1.0f);
        }
    } else if (tid == 0) {
        // fallback: global argmax (value desc, idx asc) over cell maxima
        float    bv = sval[0];
        unsigned bi = sidx[0];
        for (int j = 1; j < NCELLS; ++j) {
            if (sval[j] > bv || (sval[j] == bv && sidx[j] < bi)) { bv = sval[j]; bi = sidx[j]; }
        }
        const float px = (float)(bi & (W_DIM - 1));
        const float py = (float)(bi >> 10);
        reinterpret_cast<float4*>(orow)[0] = make_float4(px * sx, py * sy, bv, 1.0f);
    }

    const int fg_count = any_fg ? n_valid : 1;
    if (tid == 0) {
        const unsigned long long k = g_minkey[m];
        const float    bvv = __uint_as_float(((unsigned)(k >> 32)) ^ 0x80000000u);
        const unsigned bii = (unsigned)k;
        const float px = (float)(bii & (W_DIM - 1));
        const float py = (float)(bii >> 10);
        reinterpret_cast<float4*>(orow)[fg_count] =
            make_float4(px * sx, py * sy, bvv, 0.0f);
        if (write_nums)
            out[nums_off + m] = (float)(fg_count + NUM_BG);
    }
}

extern "C" void kernel_launch(void* const* d_in, const int* in_sizes, int n_in,
                              void* d_out, int out_size) {
    const float* sims = (const float*)d_in[0];
    // d_in[1] = category_ids (unused by the reference computation)
    const int* osz = (const int*)d_in[2];
    float* out = (float*)d_out;

    const int pts_elems = NMAPS * MAX_PTS * 4;                 // 5376
    const int write_nums = (out_size >= pts_elems + NMAPS) ? 1 : 0;

    k_init<<<1, 32>>>();
    k_cells<<<NMAPS * 32, 256>>>(sims);
    k_select<<<NMAPS, 256>>>(osz, out, write_nums, pts_elems);
}